// round 3
// baseline (speedup 1.0000x reference)
#include <cuda_runtime.h>
#include <math.h>

typedef unsigned long long ull;

// ---------------- scratch (device globals; no allocation allowed) ----------------
__device__ unsigned g_act1[64 * 63 * 63];          // layer1 output, 32ch packed
__device__ unsigned g_act2[64 * 31 * 31 * 2];      // layer2 output, 64ch -> 2 words
__device__ unsigned g_act3[64 * 15 * 15 * 4];      // layer3 output, 128ch -> 4 words
__device__ unsigned g_w2b[64 * 9];                 // [co][tap]
__device__ unsigned g_w3b[128 * 9 * 2];            // [co][tap][wd]
__device__ unsigned g_w4b[256 * 9 * 4];            // [co][tap][wd]
__device__ float    g_thr2[64];
__device__ float    g_thr3[128];

#define BN_EPS 1e-3f

// ---------------- f32x2 helpers (Blackwell packed fp32) ----------------
__device__ __forceinline__ ull pack2(float lo, float hi) {
    ull r; asm("mov.b64 %0, {%1, %2};" : "=l"(r) : "f"(lo), "f"(hi)); return r;
}
__device__ __forceinline__ void unpack2(float& lo, float& hi, ull v) {
    asm("mov.b64 {%0, %1}, %2;" : "=f"(lo), "=f"(hi) : "l"(v));
}
__device__ __forceinline__ ull ffma2(ull a, ull b, ull c) {
    ull d; asm("fma.rn.f32x2 %0, %1, %2, %3;" : "=l"(d) : "l"(a), "l"(b), "l"(c)); return d;
}

// ---------------- weight sign packing + BN thresholds ----------------
__global__ void k_pack(const float* __restrict__ w2,
                       const float* __restrict__ w3,
                       const float* __restrict__ w4,
                       const float* __restrict__ m2, const float* __restrict__ v2,
                       const float* __restrict__ b2,
                       const float* __restrict__ m3, const float* __restrict__ v3,
                       const float* __restrict__ b3) {
    int i = blockIdx.x * 256 + threadIdx.x;
    if (i < 576) {                       // layer2: 64co x 9tap
        int co = i / 9, t = i % 9;
        unsigned bits = 0;
        #pragma unroll
        for (int ci = 0; ci < 32; ci++)
            bits |= ((unsigned)(w2[(t * 32 + ci) * 64 + co] >= 0.f)) << ci;
        g_w2b[co * 9 + t] = bits;
    } else if (i < 576 + 2304) {         // layer3: 128co x 9tap x 2wd
        int j = i - 576;
        int co = j / 18, r = j % 18, t = r / 2, wd = r % 2;
        unsigned bits = 0;
        #pragma unroll
        for (int k = 0; k < 32; k++) {
            int ci = wd * 32 + k;
            bits |= ((unsigned)(w3[(t * 64 + ci) * 128 + co] >= 0.f)) << k;
        }
        g_w3b[(co * 9 + t) * 2 + wd] = bits;
    } else if (i < 576 + 2304 + 9216) {  // layer4: 256co x 9tap x 4wd
        int j = i - 2880;
        int co = j / 36, r = j % 36, t = r / 4, wd = r % 4;
        unsigned bits = 0;
        #pragma unroll
        for (int k = 0; k < 32; k++) {
            int ci = wd * 32 + k;
            bits |= ((unsigned)(w4[(t * 128 + ci) * 256 + co] >= 0.f)) << k;
        }
        g_w4b[(co * 9 + t) * 4 + wd] = bits;
    } else if (i < 12096 + 64) {
        int j = i - 12096;
        g_thr2[j] = m2[j] - b2[j] * sqrtf(v2[j] + BN_EPS);
    } else if (i < 12096 + 192) {
        int j = i - 12160;
        g_thr3[j] = m3[j] - b3[j] * sqrtf(v3[j] + BN_EPS);
    }
}

// ---------------- layer 1: fp32 conv(VALID) + maxpool + BN-sign, via FFMA2 ------
__global__ __launch_bounds__(256) void k_layer1(
        const float* __restrict__ x, const float* __restrict__ w1,
        const float* __restrict__ m1, const float* __restrict__ v1,
        const float* __restrict__ b1) {
    __shared__ ull sw2[32 * 28];   // [co][k] packed {s,s}
    __shared__ float thr[32];
    int tid = threadIdx.x;
    for (int i = tid; i < 864; i += 256) {
        float s = (w1[i] >= 0.f) ? 1.f : -1.f;
        int k = i >> 5, co = i & 31;
        sw2[co * 28 + k] = pack2(s, s);
    }
    if (tid < 32) thr[tid] = m1[tid] - b1[tid] * sqrtf(v1[tid] + BN_EPS);
    __syncthreads();

    int idx = blockIdx.x * 256 + tid;
    if (idx >= 64 * 63 * 63) return;
    int b = idx / 3969;
    int r = idx % 3969;
    int ph = r / 63, pw = r % 63;

    ull xa[4][9];
    const float* xb = x + (size_t)b * 128 * 128 * 3;
    #pragma unroll
    for (int i = 0; i < 4; i++) {
        const float* row = xb + ((2 * ph + i) * 128 + 2 * pw) * 3;
        float f[12];
        #pragma unroll
        for (int j = 0; j < 6; j++) {
            float2 t2 = __ldg((const float2*)row + j);
            f[2 * j] = t2.x; f[2 * j + 1] = t2.y;
        }
        #pragma unroll
        for (int kw = 0; kw < 3; kw++)
            #pragma unroll
            for (int c = 0; c < 3; c++)
                xa[i][kw * 3 + c] = pack2(f[kw * 3 + c], f[kw * 3 + c + 3]);
    }

    unsigned word = 0;
    #pragma unroll 2
    for (int co = 0; co < 32; co++) {
        const ull* wr = &sw2[co * 28];
        ull acc0 = 0ull, acc1 = 0ull;
        #pragma unroll
        for (int k = 0; k < 27; k++) {
            int kh = k / 9, rem = k % 9;
            ull w = wr[k];
            acc0 = ffma2(w, xa[kh][rem], acc0);
            acc1 = ffma2(w, xa[kh + 1][rem], acc1);
        }
        float a0, a1, a2, a3;
        unpack2(a0, a1, acc0);
        unpack2(a2, a3, acc1);
        float mx = fmaxf(fmaxf(a0, a1), fmaxf(a2, a3));
        word |= ((unsigned)(mx >= thr[co])) << co;
    }
    g_act1[idx] = word;
}

// ---------------- layer 2: warp = (b, ph, cow), loop pw with sliding window ------
__global__ __launch_bounds__(256) void k_layer2() {
    int gt = blockIdx.x * 256 + threadIdx.x;
    int gw = gt >> 5, lane = gt & 31;
    int cow = gw & 1;
    int bp = gw >> 1;                    // b*31 + ph
    int b = bp / 31, ph = bp % 31;
    int co = cow * 32 + lane;

    unsigned w[9]; int ctap[9];
    #pragma unroll
    for (int t = 0; t < 9; t++) { w[t] = g_w2b[co * 9 + t]; ctap[t] = 32 - 2 * __popc(w[t]); }
    float thr = g_thr2[co];

    const unsigned* ab = g_act1 + b * 3969;
    bool rv0 = (ph > 0);                 // row 2ph-1 valid?  (bottom always valid)
    const unsigned* rp[4];
    #pragma unroll
    for (int i = 0; i < 4; i++) rp[i] = ab + (2 * ph - 1 + i) * 63;

    unsigned a[4][4];
    #pragma unroll
    for (int i = 0; i < 4; i++) {
        bool rv = (i > 0) || rv0;
        a[i][0] = 0u;                                    // col -1
        a[i][1] = rv ? rp[i][0] : 0u;
        a[i][2] = rv ? rp[i][1] : 0u;
        a[i][3] = rv ? rp[i][2] : 0u;
    }
    unsigned* outp = g_act2 + ((b * 961) + ph * 31) * 2 + cow;

    #pragma unroll 1
    for (int pw = 0; pw < 31; pw++) {
        int P0 = 0, P1 = 0, P2 = 0, P3 = 0;
        #pragma unroll
        for (int i = 0; i < 4; i++) {
            unsigned a0 = a[i][0], a1 = a[i][1], a2 = a[i][2], a3 = a[i][3];
            if (i < 3) {
                int kh = i;
                P0 += __popc(a0 ^ w[kh * 3]) + __popc(a1 ^ w[kh * 3 + 1]) + __popc(a2 ^ w[kh * 3 + 2]);
                P1 += __popc(a1 ^ w[kh * 3]) + __popc(a2 ^ w[kh * 3 + 1]) + __popc(a3 ^ w[kh * 3 + 2]);
            }
            if (i >= 1) {
                int kh = i - 1;
                P2 += __popc(a0 ^ w[kh * 3]) + __popc(a1 ^ w[kh * 3 + 1]) + __popc(a2 ^ w[kh * 3 + 2]);
                P3 += __popc(a1 ^ w[kh * 3]) + __popc(a2 ^ w[kh * 3 + 1]) + __popc(a3 ^ w[kh * 3 + 2]);
            }
        }
        int best;
        if (rv0 && pw > 0) {
            int pmin = min(min(P0, P1), min(P2, P3));
            best = 288 - 2 * pmin;
        } else {
            int D[4] = {288 - 2 * P0, 288 - 2 * P1, 288 - 2 * P2, 288 - 2 * P3};
            #pragma unroll
            for (int dy = 0; dy < 2; dy++)
                #pragma unroll
                for (int dx = 0; dx < 2; dx++) {
                    int corr = 0;
                    #pragma unroll
                    for (int kh = 0; kh < 3; kh++)
                        #pragma unroll
                        for (int kw = 0; kw < 3; kw++)
                            if ((!rv0 && dy + kh == 0) || (pw == 0 && dx + kw == 0))
                                corr += ctap[kh * 3 + kw];
                    D[dy * 2 + dx] -= corr;
                }
            best = max(max(D[0], D[1]), max(D[2], D[3]));
        }
        unsigned word = __ballot_sync(0xffffffffu, (float)best >= thr);
        if (lane == 0) outp[pw * 2] = word;
        if (pw < 30) {
            #pragma unroll
            for (int i = 0; i < 4; i++) {
                bool rv = (i > 0) || rv0;
                a[i][0] = a[i][2]; a[i][1] = a[i][3];
                a[i][2] = rv ? rp[i][2 * pw + 3] : 0u;
                a[i][3] = rv ? rp[i][2 * pw + 4] : 0u;
            }
        }
    }
}

// ---------------- layer 3: warp = (b, ph, cow), loop pw, uint2 words -------------
__device__ __forceinline__ int popc2(uint2 a, uint2 b) {
    return __popc(a.x ^ b.x) + __popc(a.y ^ b.y);
}
__global__ __launch_bounds__(256) void k_layer3() {
    int gt = blockIdx.x * 256 + threadIdx.x;
    int gw = gt >> 5, lane = gt & 31;
    int cow = gw & 3;
    int bp = gw >> 2;                    // b*15 + ph
    int b = bp / 15, ph = bp % 15;
    int co = cow * 32 + lane;

    uint2 w[9]; int ctap[9];
    #pragma unroll
    for (int t = 0; t < 9; t++) {
        w[t] = ((const uint2*)g_w3b)[co * 9 + t];
        ctap[t] = 64 - 2 * (__popc(w[t].x) + __popc(w[t].y));
    }
    float thr = g_thr3[co];

    const uint2* ab = (const uint2*)g_act2 + b * 961;
    bool rv0 = (ph > 0);
    const uint2* rp[4];
    #pragma unroll
    for (int i = 0; i < 4; i++) rp[i] = ab + (2 * ph - 1 + i) * 31;

    uint2 a[4][4];
    #pragma unroll
    for (int i = 0; i < 4; i++) {
        bool rv = (i > 0) || rv0;
        a[i][0] = make_uint2(0u, 0u);
        a[i][1] = rv ? rp[i][0] : make_uint2(0u, 0u);
        a[i][2] = rv ? rp[i][1] : make_uint2(0u, 0u);
        a[i][3] = rv ? rp[i][2] : make_uint2(0u, 0u);
    }
    unsigned* outp = g_act3 + ((b * 225) + ph * 15) * 4 + cow;

    #pragma unroll 1
    for (int pw = 0; pw < 15; pw++) {
        int P0 = 0, P1 = 0, P2 = 0, P3 = 0;
        #pragma unroll
        for (int i = 0; i < 4; i++) {
            uint2 a0 = a[i][0], a1 = a[i][1], a2 = a[i][2], a3 = a[i][3];
            if (i < 3) {
                int kh = i;
                P0 += popc2(a0, w[kh * 3]) + popc2(a1, w[kh * 3 + 1]) + popc2(a2, w[kh * 3 + 2]);
                P1 += popc2(a1, w[kh * 3]) + popc2(a2, w[kh * 3 + 1]) + popc2(a3, w[kh * 3 + 2]);
            }
            if (i >= 1) {
                int kh = i - 1;
                P2 += popc2(a0, w[kh * 3]) + popc2(a1, w[kh * 3 + 1]) + popc2(a2, w[kh * 3 + 2]);
                P3 += popc2(a1, w[kh * 3]) + popc2(a2, w[kh * 3 + 1]) + popc2(a3, w[kh * 3 + 2]);
            }
        }
        int best;
        if (rv0 && pw > 0) {
            int pmin = min(min(P0, P1), min(P2, P3));
            best = 576 - 2 * pmin;
        } else {
            int D[4] = {576 - 2 * P0, 576 - 2 * P1, 576 - 2 * P2, 576 - 2 * P3};
            #pragma unroll
            for (int dy = 0; dy < 2; dy++)
                #pragma unroll
                for (int dx = 0; dx < 2; dx++) {
                    int corr = 0;
                    #pragma unroll
                    for (int kh = 0; kh < 3; kh++)
                        #pragma unroll
                        for (int kw = 0; kw < 3; kw++)
                            if ((!rv0 && dy + kh == 0) || (pw == 0 && dx + kw == 0))
                                corr += ctap[kh * 3 + kw];
                    D[dy * 2 + dx] -= corr;
                }
            best = max(max(D[0], D[1]), max(D[2], D[3]));
        }
        unsigned word = __ballot_sync(0xffffffffu, (float)best >= thr);
        if (lane == 0) outp[pw * 4] = word;
        if (pw < 14) {
            #pragma unroll
            for (int i = 0; i < 4; i++) {
                bool rv = (i > 0) || rv0;
                a[i][0] = a[i][2]; a[i][1] = a[i][3];
                a[i][2] = rv ? rp[i][2 * pw + 3] : make_uint2(0u, 0u);
                a[i][3] = rv ? rp[i][2 * pw + 4] : make_uint2(0u, 0u);
            }
        }
    }
}

// ---------------- layer 4: warp = (b, ph, cow), loop pw, row-streamed uint4 ------
__device__ __forceinline__ int popc4(uint4 a, uint4 b) {
    return __popc(a.x ^ b.x) + __popc(a.y ^ b.y) + __popc(a.z ^ b.z) + __popc(a.w ^ b.w);
}
__global__ __launch_bounds__(256) void k_layer4(
        const float* __restrict__ m4, const float* __restrict__ v4,
        const float* __restrict__ b4, float* __restrict__ out) {
    int gt = blockIdx.x * 256 + threadIdx.x;
    int gw = gt >> 5, lane = gt & 31;
    int cow = gw & 7;
    int bp = gw >> 3;                    // b*7 + ph
    int b = bp / 7, ph = bp % 7;
    int co = cow * 32 + lane;

    uint4 w[9]; int ctap[9];
    #pragma unroll
    for (int t = 0; t < 9; t++) {
        w[t] = ((const uint4*)g_w4b)[co * 9 + t];
        ctap[t] = 128 - 2 * (__popc(w[t].x) + __popc(w[t].y) + __popc(w[t].z) + __popc(w[t].w));
    }
    float mean = m4[co];
    float rstd = rsqrtf(v4[co] + BN_EPS);
    float beta = b4[co];

    const uint4* ab = (const uint4*)g_act3 + b * 225;
    bool rv0 = (ph > 0);
    const uint4* rp[4];
    #pragma unroll
    for (int i = 0; i < 4; i++) rp[i] = ab + (2 * ph - 1 + i) * 15;

    float* outp = out + ((b * 49) + ph * 7) * 256 + co;

    #pragma unroll 1
    for (int pw = 0; pw < 7; pw++) {
        int P0 = 0, P1 = 0, P2 = 0, P3 = 0;
        int c0 = 2 * pw - 1;
        #pragma unroll
        for (int i = 0; i < 4; i++) {
            bool rv = (i > 0) || rv0;
            uint4 z = make_uint4(0u, 0u, 0u, 0u);
            uint4 a0 = (rv && c0 >= 0) ? rp[i][c0] : z;
            uint4 a1 = rv ? rp[i][c0 + 1] : z;
            uint4 a2 = rv ? rp[i][c0 + 2] : z;
            uint4 a3 = rv ? rp[i][c0 + 3] : z;
            if (i < 3) {
                int kh = i;
                P0 += popc4(a0, w[kh * 3]) + popc4(a1, w[kh * 3 + 1]) + popc4(a2, w[kh * 3 + 2]);
                P1 += popc4(a1, w[kh * 3]) + popc4(a2, w[kh * 3 + 1]) + popc4(a3, w[kh * 3 + 2]);
            }
            if (i >= 1) {
                int kh = i - 1;
                P2 += popc4(a0, w[kh * 3]) + popc4(a1, w[kh * 3 + 1]) + popc4(a2, w[kh * 3 + 2]);
                P3 += popc4(a1, w[kh * 3]) + popc4(a2, w[kh * 3 + 1]) + popc4(a3, w[kh * 3 + 2]);
            }
        }
        int best;
        if (rv0 && pw > 0) {
            int pmin = min(min(P0, P1), min(P2, P3));
            best = 1152 - 2 * pmin;
        } else {
            int D[4] = {1152 - 2 * P0, 1152 - 2 * P1, 1152 - 2 * P2, 1152 - 2 * P3};
            #pragma unroll
            for (int dy = 0; dy < 2; dy++)
                #pragma unroll
                for (int dx = 0; dx < 2; dx++) {
                    int corr = 0;
                    #pragma unroll
                    for (int kh = 0; kh < 3; kh++)
                        #pragma unroll
                        for (int kw = 0; kw < 3; kw++)
                            if ((!rv0 && dy + kh == 0) || (pw == 0 && dx + kw == 0))
                                corr += ctap[kh * 3 + kw];
                    D[dy * 2 + dx] -= corr;
                }
            best = max(max(D[0], D[1]), max(D[2], D[3]));
        }
        outp[pw * 256] = ((float)best - mean) * rstd + beta;
    }
}

// ---------------- launch ----------------
extern "C" void kernel_launch(void* const* d_in, const int* in_sizes, int n_in,
                              void* d_out, int out_size) {
    const float* x  = (const float*)d_in[0];
    const float* w1 = (const float*)d_in[1];
    const float* m1 = (const float*)d_in[2];
    const float* v1 = (const float*)d_in[3];
    const float* b1 = (const float*)d_in[4];
    const float* w2 = (const float*)d_in[5];
    const float* m2 = (const float*)d_in[6];
    const float* v2 = (const float*)d_in[7];
    const float* b2 = (const float*)d_in[8];
    const float* w3 = (const float*)d_in[9];
    const float* m3 = (const float*)d_in[10];
    const float* v3 = (const float*)d_in[11];
    const float* b3 = (const float*)d_in[12];
    const float* w4 = (const float*)d_in[13];
    const float* m4 = (const float*)d_in[14];
    const float* v4 = (const float*)d_in[15];
    const float* b4 = (const float*)d_in[16];
    float* out = (float*)d_out;

    k_pack<<<48, 256>>>(w2, w3, w4, m2, v2, b2, m3, v3, b3);
    k_layer1<<<(64 * 63 * 63 + 255) / 256, 256>>>(x, w1, m1, v1, b1);
    k_layer2<<<(64 * 31 * 2 * 32) / 256, 256>>>();      // 496 blocks, exact
    k_layer3<<<(64 * 15 * 4 * 32) / 256, 256>>>();      // 480 blocks, exact
    k_layer4<<<(64 * 7 * 8 * 32) / 256, 256>>>(m4, v4, b4, out);  // 448 blocks, exact
}

// round 4
// speedup vs baseline: 1.0551x; 1.0551x over previous
#include <cuda_runtime.h>
#include <math.h>

typedef unsigned long long ull;

// ---------------- scratch (device globals; no allocation allowed) ----------------
__device__ unsigned g_act1[64 * 63 * 63];          // layer1 output, 32ch packed
__device__ unsigned g_act2[64 * 31 * 31 * 2];      // layer2 output, 64ch -> 2 words
__device__ unsigned g_act3[64 * 15 * 15 * 4];      // layer3 output, 128ch -> 4 words
__device__ unsigned g_w2b[64 * 9];                 // [co][tap]
__device__ unsigned g_w3b[128 * 9 * 2];            // [co][tap][wd]
__device__ unsigned g_w4b[256 * 9 * 4];            // [co][tap][wd]
__device__ float    g_thr2[64];
__device__ float    g_thr3[128];

#define BN_EPS 1e-3f

// ---------------- f32x2 helpers (Blackwell packed fp32) ----------------
__device__ __forceinline__ ull pack2(float lo, float hi) {
    ull r; asm("mov.b64 %0, {%1, %2};" : "=l"(r) : "f"(lo), "f"(hi)); return r;
}
__device__ __forceinline__ void unpack2(float& lo, float& hi, ull v) {
    asm("mov.b64 {%0, %1}, %2;" : "=f"(lo), "=f"(hi) : "l"(v));
}
__device__ __forceinline__ ull ffma2(ull a, ull b, ull c) {
    ull d; asm("fma.rn.f32x2 %0, %1, %2, %3;" : "=l"(d) : "l"(a), "l"(b), "l"(c)); return d;
}

// ---------------- weight sign packing + BN thresholds ----------------
__global__ void k_pack(const float* __restrict__ w2,
                       const float* __restrict__ w3,
                       const float* __restrict__ w4,
                       const float* __restrict__ m2, const float* __restrict__ v2,
                       const float* __restrict__ b2,
                       const float* __restrict__ m3, const float* __restrict__ v3,
                       const float* __restrict__ b3) {
    int i = blockIdx.x * 256 + threadIdx.x;
    if (i < 576) {                       // layer2: 64co x 9tap
        int co = i / 9, t = i % 9;
        unsigned bits = 0;
        #pragma unroll
        for (int ci = 0; ci < 32; ci++)
            bits |= ((unsigned)(w2[(t * 32 + ci) * 64 + co] >= 0.f)) << ci;
        g_w2b[co * 9 + t] = bits;
    } else if (i < 576 + 2304) {         // layer3: 128co x 9tap x 2wd
        int j = i - 576;
        int co = j / 18, r = j % 18, t = r / 2, wd = r % 2;
        unsigned bits = 0;
        #pragma unroll
        for (int k = 0; k < 32; k++) {
            int ci = wd * 32 + k;
            bits |= ((unsigned)(w3[(t * 64 + ci) * 128 + co] >= 0.f)) << k;
        }
        g_w3b[(co * 9 + t) * 2 + wd] = bits;
    } else if (i < 576 + 2304 + 9216) {  // layer4: 256co x 9tap x 4wd
        int j = i - 2880;
        int co = j / 36, r = j % 36, t = r / 4, wd = r % 4;
        unsigned bits = 0;
        #pragma unroll
        for (int k = 0; k < 32; k++) {
            int ci = wd * 32 + k;
            bits |= ((unsigned)(w4[(t * 128 + ci) * 256 + co] >= 0.f)) << k;
        }
        g_w4b[(co * 9 + t) * 4 + wd] = bits;
    } else if (i < 12096 + 64) {
        int j = i - 12096;
        g_thr2[j] = m2[j] - b2[j] * sqrtf(v2[j] + BN_EPS);
    } else if (i < 12096 + 192) {
        int j = i - 12160;
        g_thr3[j] = m3[j] - b3[j] * sqrtf(v3[j] + BN_EPS);
    }
}

// ---------------- layer 1: fp32 conv(VALID) + maxpool + BN-sign, via FFMA2 ------
__global__ __launch_bounds__(256) void k_layer1(
        const float* __restrict__ x, const float* __restrict__ w1,
        const float* __restrict__ m1, const float* __restrict__ v1,
        const float* __restrict__ b1) {
    __shared__ ull sw2[32 * 28];   // [co][k] packed {s,s}
    __shared__ float thr[32];
    int tid = threadIdx.x;
    for (int i = tid; i < 864; i += 256) {
        float s = (w1[i] >= 0.f) ? 1.f : -1.f;
        int k = i >> 5, co = i & 31;
        sw2[co * 28 + k] = pack2(s, s);
    }
    if (tid < 32) thr[tid] = m1[tid] - b1[tid] * sqrtf(v1[tid] + BN_EPS);
    __syncthreads();

    int idx = blockIdx.x * 256 + tid;
    if (idx >= 64 * 63 * 63) return;
    int b = idx / 3969;
    int r = idx % 3969;
    int ph = r / 63, pw = r % 63;

    ull xa[4][9];
    const float* xb = x + (size_t)b * 128 * 128 * 3;
    #pragma unroll
    for (int i = 0; i < 4; i++) {
        const float* row = xb + ((2 * ph + i) * 128 + 2 * pw) * 3;
        float f[12];
        #pragma unroll
        for (int j = 0; j < 6; j++) {
            float2 t2 = __ldg((const float2*)row + j);
            f[2 * j] = t2.x; f[2 * j + 1] = t2.y;
        }
        #pragma unroll
        for (int kw = 0; kw < 3; kw++)
            #pragma unroll
            for (int c = 0; c < 3; c++)
                xa[i][kw * 3 + c] = pack2(f[kw * 3 + c], f[kw * 3 + c + 3]);
    }

    unsigned word = 0;
    #pragma unroll 2
    for (int co = 0; co < 32; co++) {
        const ull* wr = &sw2[co * 28];
        ull acc0 = 0ull, acc1 = 0ull;
        #pragma unroll
        for (int k = 0; k < 27; k++) {
            int kh = k / 9, rem = k % 9;
            ull w = wr[k];
            acc0 = ffma2(w, xa[kh][rem], acc0);
            acc1 = ffma2(w, xa[kh + 1][rem], acc1);
        }
        float a0, a1, a2, a3;
        unpack2(a0, a1, acc0);
        unpack2(a2, a3, acc1);
        float mx = fmaxf(fmaxf(a0, a1), fmaxf(a2, a3));
        word |= ((unsigned)(mx >= thr[co])) << co;
    }
    g_act1[idx] = word;
}

// ---------------- layer 2: warp = (b, ph, cow, seg of 8 pw), sliding window ------
__global__ __launch_bounds__(256) void k_layer2() {
    const int SEG = 8;
    int gt = blockIdx.x * 256 + threadIdx.x;
    int gw = gt >> 5, lane = gt & 31;
    int seg = gw & 3;
    int t1  = gw >> 2;
    int cow = t1 & 1;
    int bp  = t1 >> 1;                    // b*31 + ph
    int b = bp / 31, ph = bp % 31;
    int co = cow * 32 + lane;
    int pw0 = seg * SEG;

    unsigned w[9];
    #pragma unroll
    for (int t = 0; t < 9; t++) w[t] = g_w2b[co * 9 + t];
    int ct[9];
    #pragma unroll
    for (int t = 0; t < 9; t++) ct[t] = 32 - 2 * __popc(w[t]);
    int corrTop = ct[0] + ct[1] + ct[2];
    int corrLeft = ct[0] + ct[3] + ct[6];
    int ctap0 = ct[0];

    int ithr = (int)ceilf(g_thr2[co]);
    int pthr = (288 - ithr) >> 1;

    const unsigned* ab = g_act1 + b * 3969;
    const unsigned* rbase = ab + (2 * ph - 1) * 63;
    bool rv0 = (ph > 0);

    unsigned a[4][4];
    #pragma unroll
    for (int i = 0; i < 4; i++) {
        bool rv = (i > 0) || rv0;
        #pragma unroll
        for (int j = 0; j < 4; j++) {
            int c = 2 * pw0 - 1 + j;
            a[i][j] = (rv && c >= 0) ? rbase[i * 63 + c] : 0u;
        }
    }
    unsigned* outp = g_act2 + (b * 961 + ph * 31) * 2 + cow;

    #pragma unroll
    for (int k = 0; k < SEG; k++) {
        int pw = pw0 + k;
        if (pw < 31) {
            int P0 = 0, P1 = 0, P2 = 0, P3 = 0;
            #pragma unroll
            for (int i = 0; i < 4; i++) {
                unsigned a0 = a[i][0], a1 = a[i][1], a2 = a[i][2], a3 = a[i][3];
                if (i < 3) {
                    int kh = i;
                    P0 += __popc(a0 ^ w[kh * 3]) + __popc(a1 ^ w[kh * 3 + 1]) + __popc(a2 ^ w[kh * 3 + 2]);
                    P1 += __popc(a1 ^ w[kh * 3]) + __popc(a2 ^ w[kh * 3 + 1]) + __popc(a3 ^ w[kh * 3 + 2]);
                }
                if (i >= 1) {
                    int kh = i - 1;
                    P2 += __popc(a0 ^ w[kh * 3]) + __popc(a1 ^ w[kh * 3 + 1]) + __popc(a2 ^ w[kh * 3 + 2]);
                    P3 += __popc(a1 ^ w[kh * 3]) + __popc(a2 ^ w[kh * 3 + 1]) + __popc(a3 ^ w[kh * 3 + 2]);
                }
            }
            bool bit;
            if (rv0 && pw > 0) {
                int pmin = min(min(P0, P1), min(P2, P3));
                bit = (pmin <= pthr);
            } else {
                int D0 = 288 - 2 * P0, D1 = 288 - 2 * P1, D2 = 288 - 2 * P2, D3 = 288 - 2 * P3;
                int cT = rv0 ? 0 : corrTop;
                int cL = (pw == 0) ? corrLeft : 0;
                int c0 = (!rv0 && pw == 0) ? ctap0 : 0;
                D0 -= cT + cL - c0; D1 -= cT; D2 -= cL;
                int best = max(max(D0, D1), max(D2, D3));
                bit = (best >= ithr);
            }
            unsigned word = __ballot_sync(0xffffffffu, bit);
            if (lane == 0) outp[pw * 2] = word;
            if (k < SEG - 1 && pw < 30) {
                #pragma unroll
                for (int i = 0; i < 4; i++) {
                    bool rv = (i > 0) || rv0;
                    a[i][0] = a[i][2]; a[i][1] = a[i][3];
                    a[i][2] = rv ? rbase[i * 63 + 2 * pw + 3] : 0u;
                    a[i][3] = rv ? rbase[i * 63 + 2 * pw + 4] : 0u;
                }
            }
        }
    }
}

// ---------------- layer 3: warp = (b, ph, cow, seg of 4 pw), uint2 window --------
__device__ __forceinline__ int popc2(uint2 a, uint2 b) {
    return __popc(a.x ^ b.x) + __popc(a.y ^ b.y);
}
__global__ __launch_bounds__(256) void k_layer3() {
    const int SEG = 4;
    int gt = blockIdx.x * 256 + threadIdx.x;
    int gw = gt >> 5, lane = gt & 31;
    int seg = gw & 3;
    int t1  = gw >> 2;
    int cow = t1 & 3;
    int bp  = t1 >> 2;                    // b*15 + ph
    int b = bp / 15, ph = bp % 15;
    int co = cow * 32 + lane;
    int pw0 = seg * SEG;

    uint2 w[9];
    #pragma unroll
    for (int t = 0; t < 9; t++) w[t] = ((const uint2*)g_w3b)[co * 9 + t];
    int ct[9];
    #pragma unroll
    for (int t = 0; t < 9; t++) ct[t] = 64 - 2 * (__popc(w[t].x) + __popc(w[t].y));
    int corrTop = ct[0] + ct[1] + ct[2];
    int corrLeft = ct[0] + ct[3] + ct[6];
    int ctap0 = ct[0];

    int ithr = (int)ceilf(g_thr3[co]);
    int pthr = (576 - ithr) >> 1;

    const uint2* ab = (const uint2*)g_act2 + b * 961;
    const uint2* rbase = ab + (2 * ph - 1) * 31;
    bool rv0 = (ph > 0);
    uint2 z = make_uint2(0u, 0u);

    uint2 a[4][4];
    #pragma unroll
    for (int i = 0; i < 4; i++) {
        bool rv = (i > 0) || rv0;
        #pragma unroll
        for (int j = 0; j < 4; j++) {
            int c = 2 * pw0 - 1 + j;
            a[i][j] = (rv && c >= 0) ? rbase[i * 31 + c] : z;
        }
    }
    unsigned* outp = g_act3 + (b * 225 + ph * 15) * 4 + cow;

    #pragma unroll
    for (int k = 0; k < SEG; k++) {
        int pw = pw0 + k;
        if (pw < 15) {
            int P0 = 0, P1 = 0, P2 = 0, P3 = 0;
            #pragma unroll
            for (int i = 0; i < 4; i++) {
                uint2 a0 = a[i][0], a1 = a[i][1], a2 = a[i][2], a3 = a[i][3];
                if (i < 3) {
                    int kh = i;
                    P0 += popc2(a0, w[kh * 3]) + popc2(a1, w[kh * 3 + 1]) + popc2(a2, w[kh * 3 + 2]);
                    P1 += popc2(a1, w[kh * 3]) + popc2(a2, w[kh * 3 + 1]) + popc2(a3, w[kh * 3 + 2]);
                }
                if (i >= 1) {
                    int kh = i - 1;
                    P2 += popc2(a0, w[kh * 3]) + popc2(a1, w[kh * 3 + 1]) + popc2(a2, w[kh * 3 + 2]);
                    P3 += popc2(a1, w[kh * 3]) + popc2(a2, w[kh * 3 + 1]) + popc2(a3, w[kh * 3 + 2]);
                }
            }
            bool bit;
            if (rv0 && pw > 0) {
                int pmin = min(min(P0, P1), min(P2, P3));
                bit = (pmin <= pthr);
            } else {
                int D0 = 576 - 2 * P0, D1 = 576 - 2 * P1, D2 = 576 - 2 * P2, D3 = 576 - 2 * P3;
                int cT = rv0 ? 0 : corrTop;
                int cL = (pw == 0) ? corrLeft : 0;
                int c0 = (!rv0 && pw == 0) ? ctap0 : 0;
                D0 -= cT + cL - c0; D1 -= cT; D2 -= cL;
                int best = max(max(D0, D1), max(D2, D3));
                bit = (best >= ithr);
            }
            unsigned word = __ballot_sync(0xffffffffu, bit);
            if (lane == 0) outp[pw * 4] = word;
            if (k < SEG - 1 && pw < 14) {
                #pragma unroll
                for (int i = 0; i < 4; i++) {
                    bool rv = (i > 0) || rv0;
                    a[i][0] = a[i][2]; a[i][1] = a[i][3];
                    a[i][2] = rv ? rbase[i * 31 + 2 * pw + 3] : z;
                    a[i][3] = rv ? rbase[i * 31 + 2 * pw + 4] : z;
                }
            }
        }
    }
}

// ---------------- layer 4: warp = (b, ph, cow, seg of 2 pw), reload uint4 --------
__device__ __forceinline__ int popc4(uint4 a, uint4 b) {
    return __popc(a.x ^ b.x) + __popc(a.y ^ b.y) + __popc(a.z ^ b.z) + __popc(a.w ^ b.w);
}
__global__ __launch_bounds__(256) void k_layer4(
        const float* __restrict__ m4, const float* __restrict__ v4,
        const float* __restrict__ b4, float* __restrict__ out) {
    const int SEG = 2;
    int gt = blockIdx.x * 256 + threadIdx.x;
    int gw = gt >> 5, lane = gt & 31;
    int seg = gw & 3;
    int t1  = gw >> 2;
    int cow = t1 & 7;
    int bp  = t1 >> 3;                    // b*7 + ph
    int b = bp / 7, ph = bp % 7;
    int co = cow * 32 + lane;
    int pw0 = seg * SEG;

    uint4 w[9];
    #pragma unroll
    for (int t = 0; t < 9; t++) w[t] = ((const uint4*)g_w4b)[co * 9 + t];
    int ct[9];
    #pragma unroll
    for (int t = 0; t < 9; t++)
        ct[t] = 128 - 2 * (__popc(w[t].x) + __popc(w[t].y) + __popc(w[t].z) + __popc(w[t].w));
    int corrTop = ct[0] + ct[1] + ct[2];
    int corrLeft = ct[0] + ct[3] + ct[6];
    int ctap0 = ct[0];

    float mean = m4[co];
    float rstd = rsqrtf(v4[co] + BN_EPS);
    float beta = b4[co];

    const uint4* ab = (const uint4*)g_act3 + b * 225;
    const uint4* rbase = ab + (2 * ph - 1) * 15;
    bool rv0 = (ph > 0);
    uint4 z = make_uint4(0u, 0u, 0u, 0u);

    float* outp = out + (b * 49 + ph * 7) * 256 + co;

    #pragma unroll
    for (int k = 0; k < SEG; k++) {
        int pw = pw0 + k;
        if (pw < 7) {
            int c0 = 2 * pw - 1;
            int P0 = 0, P1 = 0, P2 = 0, P3 = 0;
            #pragma unroll
            for (int i = 0; i < 4; i++) {
                bool rv = (i > 0) || rv0;
                uint4 a0 = (rv && c0 >= 0) ? rbase[i * 15 + c0] : z;
                uint4 a1 = rv ? rbase[i * 15 + c0 + 1] : z;
                uint4 a2 = rv ? rbase[i * 15 + c0 + 2] : z;
                uint4 a3 = rv ? rbase[i * 15 + c0 + 3] : z;
                if (i < 3) {
                    int kh = i;
                    P0 += popc4(a0, w[kh * 3]) + popc4(a1, w[kh * 3 + 1]) + popc4(a2, w[kh * 3 + 2]);
                    P1 += popc4(a1, w[kh * 3]) + popc4(a2, w[kh * 3 + 1]) + popc4(a3, w[kh * 3 + 2]);
                }
                if (i >= 1) {
                    int kh = i - 1;
                    P2 += popc4(a0, w[kh * 3]) + popc4(a1, w[kh * 3 + 1]) + popc4(a2, w[kh * 3 + 2]);
                    P3 += popc4(a1, w[kh * 3]) + popc4(a2, w[kh * 3 + 1]) + popc4(a3, w[kh * 3 + 2]);
                }
            }
            int best;
            if (rv0 && pw > 0) {
                int pmin = min(min(P0, P1), min(P2, P3));
                best = 1152 - 2 * pmin;
            } else {
                int D0 = 1152 - 2 * P0, D1 = 1152 - 2 * P1, D2 = 1152 - 2 * P2, D3 = 1152 - 2 * P3;
                int cT = rv0 ? 0 : corrTop;
                int cL = (pw == 0) ? corrLeft : 0;
                int c0c = (!rv0 && pw == 0) ? ctap0 : 0;
                D0 -= cT + cL - c0c; D1 -= cT; D2 -= cL;
                best = max(max(D0, D1), max(D2, D3));
            }
            outp[pw * 256] = ((float)best - mean) * rstd + beta;
        }
    }
}

// ---------------- launch ----------------
extern "C" void kernel_launch(void* const* d_in, const int* in_sizes, int n_in,
                              void* d_out, int out_size) {
    const float* x  = (const float*)d_in[0];
    const float* w1 = (const float*)d_in[1];
    const float* m1 = (const float*)d_in[2];
    const float* v1 = (const float*)d_in[3];
    const float* b1 = (const float*)d_in[4];
    const float* w2 = (const float*)d_in[5];
    const float* m2 = (const float*)d_in[6];
    const float* v2 = (const float*)d_in[7];
    const float* b2 = (const float*)d_in[8];
    const float* w3 = (const float*)d_in[9];
    const float* m3 = (const float*)d_in[10];
    const float* v3 = (const float*)d_in[11];
    const float* b3 = (const float*)d_in[12];
    const float* w4 = (const float*)d_in[13];
    const float* m4 = (const float*)d_in[14];
    const float* v4 = (const float*)d_in[15];
    const float* b4 = (const float*)d_in[16];
    float* out = (float*)d_out;

    k_pack<<<48, 256>>>(w2, w3, w4, m2, v2, b2, m3, v3, b3);
    k_layer1<<<(64 * 63 * 63 + 255) / 256, 256>>>(x, w1, m1, v1, b1);
    k_layer2<<<64 * 31 * 2 * 4 / 8, 256>>>();          // 1984 blocks
    k_layer3<<<64 * 15 * 4 * 4 / 8, 256>>>();          // 1920 blocks
    k_layer4<<<64 * 7 * 8 * 4 / 8, 256>>>(m4, v4, b4, out);  // 1792 blocks
}

// round 5
// speedup vs baseline: 1.1263x; 1.0676x over previous
#include <cuda_runtime.h>
#include <math.h>

typedef unsigned long long ull;
typedef unsigned u32;

// ---------------- scratch (device globals; no allocation allowed) ----------------
__device__ u32 g_act1[64 * 63 * 63];          // layer1 output, 32ch packed
__device__ u32 g_act2[64 * 31 * 31 * 2];      // layer2 output, 64ch -> 2 words
__device__ u32 g_act3[64 * 15 * 15 * 4];      // layer3 output, 128ch -> 4 words
__device__ u32 g_w2b[64 * 9];                 // [co][tap]
__device__ u32 g_w3b[128 * 9 * 2];            // [co][tap][wd]
__device__ u32 g_w4b[256 * 9 * 4];            // [co][tap][wd]
__device__ float g_thr2[64];
__device__ float g_thr3[128];

#define BN_EPS 1e-3f

// ---------------- f32x2 helpers ----------------
__device__ __forceinline__ ull pack2(float lo, float hi) {
    ull r; asm("mov.b64 %0, {%1, %2};" : "=l"(r) : "f"(lo), "f"(hi)); return r;
}
__device__ __forceinline__ void unpack2(float& lo, float& hi, ull v) {
    asm("mov.b64 {%0, %1}, %2;" : "=f"(lo), "=f"(hi) : "l"(v));
}
__device__ __forceinline__ ull ffma2(ull a, ull b, ull c) {
    ull d; asm("fma.rn.f32x2 %0, %1, %2, %3;" : "=l"(d) : "l"(a), "l"(b), "l"(c)); return d;
}

// ---------------- CSA popcount machinery (LOP3-rate, few POPCs) ----------------
__device__ __forceinline__ void CSA(u32& s, u32& c, u32 a, u32 b, u32 d) {
    u32 t = a ^ b;
    s = t ^ d;                 // LOP3 0x96
    c = (a & b) | (t & d);     // LOP3 0xE8
}

// sum of popcounts of 9 words: 14 LOP3 + 4 POPC (vs 9 POPC)
__device__ __forceinline__ int R9(u32 x0, u32 x1, u32 x2, u32 x3, u32 x4,
                                  u32 x5, u32 x6, u32 x7, u32 x8) {
    u32 s0, c0, s1, c1, s2, c2, s3, c3, s4, c4;
    CSA(s0, c0, x0, x1, x2);
    CSA(s1, c1, x3, x4, x5);
    CSA(s2, c2, x6, x7, x8);
    CSA(s3, c3, s0, s1, s2);       // s3: w1 final, c3: w2
    CSA(s4, c4, c0, c1, c2);       // s4: w2, c4: w4
    u32 s5 = s4 ^ c3, c5 = s4 & c3;    // w2 final s5, carry w4
    u32 s6 = c4 ^ c5, c6 = c4 & c5;    // w4 final s6, carry w8
    return __popc(s3) + 2 * __popc(s5) + 4 * __popc(s6) + 8 * __popc(c6);
}

// sum of popcounts of 18 words: 32 LOP3 + 5 POPC (vs 18 POPC)
__device__ __forceinline__ int R18(const u32 x[18]) {
    u32 a0, b0, a1, b1, a2, b2, a3, b3, a4, b4, a5, b5;
    CSA(a0, b0, x[0], x[1], x[2]);
    CSA(a1, b1, x[3], x[4], x[5]);
    CSA(a2, b2, x[6], x[7], x[8]);
    CSA(a3, b3, x[9], x[10], x[11]);
    CSA(a4, b4, x[12], x[13], x[14]);
    CSA(a5, b5, x[15], x[16], x[17]);
    u32 t0, d0, t1, d1;
    CSA(t0, d0, a0, a1, a2);
    CSA(t1, d1, a3, a4, a5);
    u32 u0 = t0 ^ t1, e0 = t0 & t1;    // u0: w1 final; e0: w2
    int P2 = R9(b0, b1, b2, b3, b4, b5, d0, d1, e0);   // value in units of w2
    return __popc(u0) + 2 * P2;
}

// ---------------- weight sign packing + BN thresholds ----------------
__global__ void k_pack(const float* __restrict__ w2,
                       const float* __restrict__ w3,
                       const float* __restrict__ w4,
                       const float* __restrict__ m2, const float* __restrict__ v2,
                       const float* __restrict__ b2,
                       const float* __restrict__ m3, const float* __restrict__ v3,
                       const float* __restrict__ b3) {
    int i = blockIdx.x * 256 + threadIdx.x;
    if (i < 576) {                       // layer2: 64co x 9tap
        int co = i / 9, t = i % 9;
        u32 bits = 0;
        #pragma unroll
        for (int ci = 0; ci < 32; ci++)
            bits |= ((u32)(w2[(t * 32 + ci) * 64 + co] >= 0.f)) << ci;
        g_w2b[co * 9 + t] = bits;
    } else if (i < 576 + 2304) {         // layer3: 128co x 9tap x 2wd
        int j = i - 576;
        int co = j / 18, r = j % 18, t = r / 2, wd = r % 2;
        u32 bits = 0;
        #pragma unroll
        for (int k = 0; k < 32; k++) {
            int ci = wd * 32 + k;
            bits |= ((u32)(w3[(t * 64 + ci) * 128 + co] >= 0.f)) << k;
        }
        g_w3b[(co * 9 + t) * 2 + wd] = bits;
    } else if (i < 576 + 2304 + 9216) {  // layer4: 256co x 9tap x 4wd
        int j = i - 2880;
        int co = j / 36, r = j % 36, t = r / 4, wd = r % 4;
        u32 bits = 0;
        #pragma unroll
        for (int k = 0; k < 32; k++) {
            int ci = wd * 32 + k;
            bits |= ((u32)(w4[(t * 128 + ci) * 256 + co] >= 0.f)) << k;
        }
        g_w4b[(co * 9 + t) * 4 + wd] = bits;
    } else if (i < 12096 + 64) {
        int j = i - 12096;
        g_thr2[j] = m2[j] - b2[j] * sqrtf(v2[j] + BN_EPS);
    } else if (i < 12096 + 192) {
        int j = i - 12160;
        g_thr3[j] = m3[j] - b3[j] * sqrtf(v3[j] + BN_EPS);
    }
}

// ---------------- layer 1: fp32 conv(VALID) + maxpool + BN-sign, via FFMA2 ------
__global__ __launch_bounds__(256) void k_layer1(
        const float* __restrict__ x, const float* __restrict__ w1,
        const float* __restrict__ m1, const float* __restrict__ v1,
        const float* __restrict__ b1) {
    __shared__ ull sw2[32 * 28];   // [co][k] packed {s,s}
    __shared__ float thr[32];
    int tid = threadIdx.x;
    for (int i = tid; i < 864; i += 256) {
        float s = (w1[i] >= 0.f) ? 1.f : -1.f;
        int k = i >> 5, co = i & 31;
        sw2[co * 28 + k] = pack2(s, s);
    }
    if (tid < 32) thr[tid] = m1[tid] - b1[tid] * sqrtf(v1[tid] + BN_EPS);
    __syncthreads();

    int idx = blockIdx.x * 256 + tid;
    if (idx >= 64 * 63 * 63) return;
    int b = idx / 3969;
    int r = idx % 3969;
    int ph = r / 63, pw = r % 63;

    ull xa[4][9];
    const float* xb = x + (size_t)b * 128 * 128 * 3;
    #pragma unroll
    for (int i = 0; i < 4; i++) {
        const float* row = xb + ((2 * ph + i) * 128 + 2 * pw) * 3;
        float f[12];
        #pragma unroll
        for (int j = 0; j < 6; j++) {
            float2 t2 = __ldg((const float2*)row + j);
            f[2 * j] = t2.x; f[2 * j + 1] = t2.y;
        }
        #pragma unroll
        for (int kw = 0; kw < 3; kw++)
            #pragma unroll
            for (int c = 0; c < 3; c++)
                xa[i][kw * 3 + c] = pack2(f[kw * 3 + c], f[kw * 3 + c + 3]);
    }

    u32 word = 0;
    #pragma unroll 2
    for (int co = 0; co < 32; co++) {
        const ull* wr = &sw2[co * 28];
        ull acc0 = 0ull, acc1 = 0ull;
        #pragma unroll
        for (int k = 0; k < 27; k++) {
            int kh = k / 9, rem = k % 9;
            ull w = wr[k];
            acc0 = ffma2(w, xa[kh][rem], acc0);
            acc1 = ffma2(w, xa[kh + 1][rem], acc1);
        }
        float a0, a1, a2, a3;
        unpack2(a0, a1, acc0);
        unpack2(a2, a3, acc1);
        float mx = fmaxf(fmaxf(a0, a1), fmaxf(a2, a3));
        word |= ((u32)(mx >= thr[co])) << co;
    }
    g_act1[idx] = word;
}

// ---------------- layer 2: warp = position, lane = 2 channels (co, co+32) --------
__global__ __launch_bounds__(256) void k_layer2() {
    int gt = blockIdx.x * 256 + threadIdx.x;
    int gw = gt >> 5, lane = gt & 31;           // gw = position p in [0, 64*961)
    int b = gw / 961, r = gw % 961;
    int ph = r / 31, pw = r % 31;

    u32 wA[9], wB[9];
    #pragma unroll
    for (int t = 0; t < 9; t++) {
        wA[t] = g_w2b[lane * 9 + t];
        wB[t] = g_w2b[(lane + 32) * 9 + t];
    }
    int ithrA = (int)ceilf(g_thr2[lane]);
    int ithrB = (int)ceilf(g_thr2[lane + 32]);

    const u32* rbase = g_act1 + b * 3969 + (2 * ph - 1) * 63;
    bool rv0 = (ph > 0), cv0 = (pw > 0);

    u32 a[4][4];
    #pragma unroll
    for (int i = 0; i < 4; i++) {
        bool rv = (i > 0) || rv0;
        #pragma unroll
        for (int j = 0; j < 4; j++) {
            bool cv = (j > 0) || cv0;
            a[i][j] = (rv && cv) ? rbase[i * 63 + 2 * pw - 1 + j] : 0u;
        }
    }

    int PA[4], PB[4];
    #pragma unroll
    for (int dy = 0; dy < 2; dy++)
        #pragma unroll
        for (int dx = 0; dx < 2; dx++) {
            PA[dy * 2 + dx] = R9(a[dy][dx] ^ wA[0], a[dy][dx + 1] ^ wA[1], a[dy][dx + 2] ^ wA[2],
                                 a[dy + 1][dx] ^ wA[3], a[dy + 1][dx + 1] ^ wA[4], a[dy + 1][dx + 2] ^ wA[5],
                                 a[dy + 2][dx] ^ wA[6], a[dy + 2][dx + 1] ^ wA[7], a[dy + 2][dx + 2] ^ wA[8]);
            PB[dy * 2 + dx] = R9(a[dy][dx] ^ wB[0], a[dy][dx + 1] ^ wB[1], a[dy][dx + 2] ^ wB[2],
                                 a[dy + 1][dx] ^ wB[3], a[dy + 1][dx + 1] ^ wB[4], a[dy + 1][dx + 2] ^ wB[5],
                                 a[dy + 2][dx] ^ wB[6], a[dy + 2][dx + 1] ^ wB[7], a[dy + 2][dx + 2] ^ wB[8]);
        }

    bool bitA, bitB;
    if (rv0 && cv0) {
        int pthrA = (288 - ithrA) >> 1;
        int pthrB = (288 - ithrB) >> 1;
        bitA = min(min(PA[0], PA[1]), min(PA[2], PA[3])) <= pthrA;
        bitB = min(min(PB[0], PB[1]), min(PB[2], PB[3])) <= pthrB;
    } else {
        int ctA[9], ctB[9];
        #pragma unroll
        for (int t = 0; t < 9; t++) {
            ctA[t] = 32 - 2 * __popc(wA[t]);
            ctB[t] = 32 - 2 * __popc(wB[t]);
        }
        int topA = ctA[0] + ctA[1] + ctA[2], leftA = ctA[0] + ctA[3] + ctA[6];
        int topB = ctB[0] + ctB[1] + ctB[2], leftB = ctB[0] + ctB[3] + ctB[6];
        int cTA = rv0 ? 0 : topA, cLA = cv0 ? 0 : leftA, c0A = (!rv0 && !cv0) ? ctA[0] : 0;
        int cTB = rv0 ? 0 : topB, cLB = cv0 ? 0 : leftB, c0B = (!rv0 && !cv0) ? ctB[0] : 0;
        int DA0 = 288 - 2 * PA[0] - (cTA + cLA - c0A);
        int DA1 = 288 - 2 * PA[1] - cTA;
        int DA2 = 288 - 2 * PA[2] - cLA;
        int DA3 = 288 - 2 * PA[3];
        int DB0 = 288 - 2 * PB[0] - (cTB + cLB - c0B);
        int DB1 = 288 - 2 * PB[1] - cTB;
        int DB2 = 288 - 2 * PB[2] - cLB;
        int DB3 = 288 - 2 * PB[3];
        bitA = max(max(DA0, DA1), max(DA2, DA3)) >= ithrA;
        bitB = max(max(DB0, DB1), max(DB2, DB3)) >= ithrB;
    }
    u32 wordA = __ballot_sync(0xffffffffu, bitA);
    u32 wordB = __ballot_sync(0xffffffffu, bitB);
    if (lane == 0) ((uint2*)g_act2)[gw] = make_uint2(wordA, wordB);
}

// ---------------- layer 3 window helper (compile-time dy,dx) ---------------------
template <int DY, int DX>
__device__ __forceinline__ int win18(const uint2 (&a)[4][4], const uint2 (&w)[9]) {
    u32 x[18];
    #pragma unroll
    for (int kh = 0; kh < 3; kh++)
        #pragma unroll
        for (int kw = 0; kw < 3; kw++) {
            int t = kh * 3 + kw;
            x[2 * t]     = a[DY + kh][DX + kw].x ^ w[t].x;
            x[2 * t + 1] = a[DY + kh][DX + kw].y ^ w[t].y;
        }
    return R18(x);
}

// ---------------- layer 3: warp = (position, cow), CSA popcount ------------------
__global__ __launch_bounds__(256) void k_layer3() {
    int gt = blockIdx.x * 256 + threadIdx.x;
    int gw = gt >> 5, lane = gt & 31;
    int cow = gw & 3;
    int p = gw >> 2;
    int b = p / 225, r = p % 225;
    int ph = r / 15, pw = r % 15;
    int co = cow * 32 + lane;

    uint2 w[9];
    #pragma unroll
    for (int t = 0; t < 9; t++) w[t] = ((const uint2*)g_w3b)[co * 9 + t];
    int ithr = (int)ceilf(g_thr3[co]);

    const uint2* rbase = (const uint2*)g_act2 + b * 961 + (2 * ph - 1) * 31;
    bool rv0 = (ph > 0), cv0 = (pw > 0);
    uint2 z = make_uint2(0u, 0u);

    uint2 a[4][4];
    #pragma unroll
    for (int i = 0; i < 4; i++) {
        bool rv = (i > 0) || rv0;
        #pragma unroll
        for (int j = 0; j < 4; j++) {
            bool cv = (j > 0) || cv0;
            a[i][j] = (rv && cv) ? rbase[i * 31 + 2 * pw - 1 + j] : z;
        }
    }

    int P0 = win18<0, 0>(a, w);
    int P1 = win18<0, 1>(a, w);
    int P2 = win18<1, 0>(a, w);
    int P3 = win18<1, 1>(a, w);

    bool bit;
    if (rv0 && cv0) {
        int pthr = (576 - ithr) >> 1;
        bit = min(min(P0, P1), min(P2, P3)) <= pthr;
    } else {
        int ct[9];
        #pragma unroll
        for (int t = 0; t < 9; t++) ct[t] = 64 - 2 * (__popc(w[t].x) + __popc(w[t].y));
        int top = ct[0] + ct[1] + ct[2], left = ct[0] + ct[3] + ct[6];
        int cT = rv0 ? 0 : top, cL = cv0 ? 0 : left, c0 = (!rv0 && !cv0) ? ct[0] : 0;
        int D0 = 576 - 2 * P0 - (cT + cL - c0);
        int D1 = 576 - 2 * P1 - cT;
        int D2 = 576 - 2 * P2 - cL;
        int D3 = 576 - 2 * P3;
        bit = max(max(D0, D1), max(D2, D3)) >= ithr;
    }
    u32 word = __ballot_sync(0xffffffffu, bit);
    if (lane == 0) g_act3[p * 4 + cow] = word;
}

// ---------------- layer 4: warp = (position, cow), 2 passes of uint2 halves ------
__global__ __launch_bounds__(256) void k_layer4(
        const float* __restrict__ m4, const float* __restrict__ v4,
        const float* __restrict__ b4, float* __restrict__ out) {
    int gt = blockIdx.x * 256 + threadIdx.x;
    int gw = gt >> 5, lane = gt & 31;
    int cow = gw & 7;
    int p = gw >> 3;
    int b = p / 49, r = p % 49;
    int ph = r / 7, pw = r % 7;
    int co = cow * 32 + lane;

    const uint2* act = (const uint2*)g_act3;   // uint4 cells viewed as 2x uint2
    bool rv0 = (ph > 0), cv0 = (pw > 0);
    uint2 z = make_uint2(0u, 0u);

    int P0 = 0, P1 = 0, P2 = 0, P3 = 0;
    #pragma unroll
    for (int h = 0; h < 2; h++) {
        uint2 w[9];
        #pragma unroll
        for (int t = 0; t < 9; t++) w[t] = ((const uint2*)g_w4b)[(co * 9 + t) * 2 + h];

        uint2 a[4][4];
        #pragma unroll
        for (int i = 0; i < 4; i++) {
            bool rv = (i > 0) || rv0;
            #pragma unroll
            for (int j = 0; j < 4; j++) {
                bool cv = (j > 0) || cv0;
                int rr = 2 * ph - 1 + i, cc = 2 * pw - 1 + j;
                a[i][j] = (rv && cv) ? act[(b * 225 + rr * 15 + cc) * 2 + h] : z;
            }
        }
        P0 += win18<0, 0>(a, w);
        P1 += win18<0, 1>(a, w);
        P2 += win18<1, 0>(a, w);
        P3 += win18<1, 1>(a, w);
    }

    int best;
    if (rv0 && cv0) {
        int pmin = min(min(P0, P1), min(P2, P3));
        best = 1152 - 2 * pmin;
    } else {
        int ct[9];
        #pragma unroll
        for (int t = 0; t < 9; t++) {
            uint4 wt = ((const uint4*)g_w4b)[co * 9 + t];
            ct[t] = 128 - 2 * (__popc(wt.x) + __popc(wt.y) + __popc(wt.z) + __popc(wt.w));
        }
        int top = ct[0] + ct[1] + ct[2], left = ct[0] + ct[3] + ct[6];
        int cT = rv0 ? 0 : top, cL = cv0 ? 0 : left, c0 = (!rv0 && !cv0) ? ct[0] : 0;
        int D0 = 1152 - 2 * P0 - (cT + cL - c0);
        int D1 = 1152 - 2 * P1 - cT;
        int D2 = 1152 - 2 * P2 - cL;
        int D3 = 1152 - 2 * P3;
        best = max(max(D0, D1), max(D2, D3));
    }
    float o = ((float)best - m4[co]) * rsqrtf(v4[co] + BN_EPS) + b4[co];
    out[p * 256 + co] = o;
}

// ---------------- launch ----------------
extern "C" void kernel_launch(void* const* d_in, const int* in_sizes, int n_in,
                              void* d_out, int out_size) {
    const float* x  = (const float*)d_in[0];
    const float* w1 = (const float*)d_in[1];
    const float* m1 = (const float*)d_in[2];
    const float* v1 = (const float*)d_in[3];
    const float* b1 = (const float*)d_in[4];
    const float* w2 = (const float*)d_in[5];
    const float* m2 = (const float*)d_in[6];
    const float* v2 = (const float*)d_in[7];
    const float* b2 = (const float*)d_in[8];
    const float* w3 = (const float*)d_in[9];
    const float* m3 = (const float*)d_in[10];
    const float* v3 = (const float*)d_in[11];
    const float* b3 = (const float*)d_in[12];
    const float* w4 = (const float*)d_in[13];
    const float* m4 = (const float*)d_in[14];
    const float* v4 = (const float*)d_in[15];
    const float* b4 = (const float*)d_in[16];
    float* out = (float*)d_out;

    k_pack<<<48, 256>>>(w2, w3, w4, m2, v2, b2, m3, v3, b3);
    k_layer1<<<(64 * 63 * 63 + 255) / 256, 256>>>(x, w1, m1, v1, b1);
    k_layer2<<<64 * 961 * 32 / 256, 256>>>();           // 7688 blocks
    k_layer3<<<64 * 225 * 4 * 32 / 256, 256>>>();       // 7200 blocks
    k_layer4<<<64 * 49 * 8 * 32 / 256, 256>>>(m4, v4, b4, out);  // 3136 blocks
}

// round 6
// speedup vs baseline: 1.1934x; 1.0595x over previous
#include <cuda_runtime.h>
#include <math.h>

typedef unsigned long long ull;
typedef unsigned u32;

// ---------------- scratch (device globals; no allocation allowed) ----------------
__device__ u32 g_act1[64 * 63 * 63];          // layer1 output, 32ch packed
__device__ u32 g_act2[64 * 31 * 31 * 2];      // layer2 output, 64ch -> 2 words
__device__ u32 g_act3[64 * 15 * 15 * 4];      // layer3 output, 128ch -> 4 words
__device__ u32 g_w2b[64 * 9];                 // [co][tap]
__device__ u32 g_w3b[128 * 9 * 2];            // [co][tap][wd]
__device__ u32 g_w4b[256 * 9 * 4];            // [co][tap][wd]
__device__ float g_thr2[64];
__device__ float g_thr3[128];

#define BN_EPS 1e-3f

// ---------------- f32x2 helpers ----------------
__device__ __forceinline__ ull pack2(float lo, float hi) {
    ull r; asm("mov.b64 %0, {%1, %2};" : "=l"(r) : "f"(lo), "f"(hi)); return r;
}
__device__ __forceinline__ void unpack2(float& lo, float& hi, ull v) {
    asm("mov.b64 {%0, %1}, %2;" : "=f"(lo), "=f"(hi) : "l"(v));
}
__device__ __forceinline__ ull ffma2(ull a, ull b, ull c) {
    ull d; asm("fma.rn.f32x2 %0, %1, %2, %3;" : "=l"(d) : "l"(a), "l"(b), "l"(c)); return d;
}

// ---------------- CSA popcount machinery (LOP3-rate, few POPCs) ----------------
__device__ __forceinline__ void CSA(u32& s, u32& c, u32 a, u32 b, u32 d) {
    u32 t = a ^ b;
    s = t ^ d;                 // LOP3 0x96
    c = (a & b) | (t & d);     // LOP3 0xE8
}

// sum of popcounts of 9 words: 14 LOP3 + 4 POPC
__device__ __forceinline__ int R9(u32 x0, u32 x1, u32 x2, u32 x3, u32 x4,
                                  u32 x5, u32 x6, u32 x7, u32 x8) {
    u32 s0, c0, s1, c1, s2, c2, s3, c3, s4, c4;
    CSA(s0, c0, x0, x1, x2);
    CSA(s1, c1, x3, x4, x5);
    CSA(s2, c2, x6, x7, x8);
    CSA(s3, c3, s0, s1, s2);
    CSA(s4, c4, c0, c1, c2);
    u32 s5 = s4 ^ c3, c5 = s4 & c3;
    u32 s6 = c4 ^ c5, c6 = c4 & c5;
    return __popc(s3) + 2 * __popc(s5) + 4 * __popc(s6) + 8 * __popc(c6);
}

// sum of popcounts of 18 words: 32 LOP3 + 5 POPC
__device__ __forceinline__ int R18(const u32 x[18]) {
    u32 a0, b0, a1, b1, a2, b2, a3, b3, a4, b4, a5, b5;
    CSA(a0, b0, x[0], x[1], x[2]);
    CSA(a1, b1, x[3], x[4], x[5]);
    CSA(a2, b2, x[6], x[7], x[8]);
    CSA(a3, b3, x[9], x[10], x[11]);
    CSA(a4, b4, x[12], x[13], x[14]);
    CSA(a5, b5, x[15], x[16], x[17]);
    u32 t0, d0, t1, d1;
    CSA(t0, d0, a0, a1, a2);
    CSA(t1, d1, a3, a4, a5);
    u32 u0 = t0 ^ t1, e0 = t0 & t1;
    int P2 = R9(b0, b1, b2, b3, b4, b5, d0, d1, e0);
    return __popc(u0) + 2 * P2;
}

template <int DY, int DX>
__device__ __forceinline__ int win18(const uint2 (&a)[4][4], const uint2 (&w)[9]) {
    u32 x[18];
    #pragma unroll
    for (int kh = 0; kh < 3; kh++)
        #pragma unroll
        for (int kw = 0; kw < 3; kw++) {
            int t = kh * 3 + kw;
            x[2 * t]     = a[DY + kh][DX + kw].x ^ w[t].x;
            x[2 * t + 1] = a[DY + kh][DX + kw].y ^ w[t].y;
        }
    return R18(x);
}

// ---------------- weight sign packing + thresholds (device function) ------------
__device__ void do_pack(int i,
                        const float* __restrict__ w2, const float* __restrict__ w3,
                        const float* __restrict__ w4,
                        const float* __restrict__ m2, const float* __restrict__ v2,
                        const float* __restrict__ b2,
                        const float* __restrict__ m3, const float* __restrict__ v3,
                        const float* __restrict__ b3) {
    if (i < 576) {                       // layer2: 64co x 9tap
        int co = i / 9, t = i % 9;
        u32 bits = 0;
        #pragma unroll
        for (int ci = 0; ci < 32; ci++)
            bits |= ((u32)(w2[(t * 32 + ci) * 64 + co] >= 0.f)) << ci;
        g_w2b[co * 9 + t] = bits;
    } else if (i < 576 + 2304) {         // layer3: 128co x 9tap x 2wd
        int j = i - 576;
        int co = j / 18, r = j % 18, t = r / 2, wd = r % 2;
        u32 bits = 0;
        #pragma unroll
        for (int k = 0; k < 32; k++) {
            int ci = wd * 32 + k;
            bits |= ((u32)(w3[(t * 64 + ci) * 128 + co] >= 0.f)) << k;
        }
        g_w3b[(co * 9 + t) * 2 + wd] = bits;
    } else if (i < 576 + 2304 + 9216) {  // layer4: 256co x 9tap x 4wd
        int j = i - 2880;
        int co = j / 36, r = j % 36, t = r / 4, wd = r % 4;
        u32 bits = 0;
        #pragma unroll
        for (int k = 0; k < 32; k++) {
            int ci = wd * 32 + k;
            bits |= ((u32)(w4[(t * 128 + ci) * 256 + co] >= 0.f)) << k;
        }
        g_w4b[(co * 9 + t) * 4 + wd] = bits;
    } else if (i < 12096 + 64) {
        int j = i - 12096;
        g_thr2[j] = m2[j] - b2[j] * sqrtf(v2[j] + BN_EPS);
    } else if (i < 12096 + 192) {
        int j = i - 12160;
        g_thr3[j] = m3[j] - b3[j] * sqrtf(v3[j] + BN_EPS);
    }
}

#define NB1 993   // layer1 blocks

// ---------------- layer 1 (+48 pack blocks): fp32 conv + maxpool + BN-sign ------
__global__ __launch_bounds__(256) void k_layer1(
        const float* __restrict__ x, const float* __restrict__ w1,
        const float* __restrict__ m1, const float* __restrict__ v1,
        const float* __restrict__ b1,
        const float* __restrict__ w2, const float* __restrict__ w3,
        const float* __restrict__ w4,
        const float* __restrict__ m2, const float* __restrict__ v2,
        const float* __restrict__ b2,
        const float* __restrict__ m3, const float* __restrict__ v3,
        const float* __restrict__ b3) {
    int tid = threadIdx.x;
    if (blockIdx.x >= NB1) {    // pack path
        int i = (blockIdx.x - NB1) * 256 + tid;
        do_pack(i, w2, w3, w4, m2, v2, b2, m3, v3, b3);
        return;
    }
    __shared__ ull sw2[32 * 28];   // [co][k] packed {s,s}
    __shared__ float thr[32];
    for (int i = tid; i < 864; i += 256) {
        float s = (w1[i] >= 0.f) ? 1.f : -1.f;
        int k = i >> 5, co = i & 31;
        sw2[co * 28 + k] = pack2(s, s);
    }
    if (tid < 32) thr[tid] = m1[tid] - b1[tid] * sqrtf(v1[tid] + BN_EPS);
    __syncthreads();

    int idx = blockIdx.x * 256 + tid;
    if (idx >= 64 * 63 * 63) return;
    int b = idx / 3969;
    int r = idx % 3969;
    int ph = r / 63, pw = r % 63;

    ull xa[4][9];
    const float* xb = x + (size_t)b * 128 * 128 * 3;
    #pragma unroll
    for (int i = 0; i < 4; i++) {
        const float* row = xb + ((2 * ph + i) * 128 + 2 * pw) * 3;
        float f[12];
        #pragma unroll
        for (int j = 0; j < 6; j++) {
            float2 t2 = __ldg((const float2*)row + j);
            f[2 * j] = t2.x; f[2 * j + 1] = t2.y;
        }
        #pragma unroll
        for (int kw = 0; kw < 3; kw++)
            #pragma unroll
            for (int c = 0; c < 3; c++)
                xa[i][kw * 3 + c] = pack2(f[kw * 3 + c], f[kw * 3 + c + 3]);
    }

    u32 word = 0;
    #pragma unroll 2
    for (int co = 0; co < 32; co++) {
        const ull* wr = &sw2[co * 28];
        ull acc0 = 0ull, acc1 = 0ull;
        #pragma unroll
        for (int k = 0; k < 27; k++) {
            int kh = k / 9, rem = k % 9;
            ull w = wr[k];
            acc0 = ffma2(w, xa[kh][rem], acc0);
            acc1 = ffma2(w, xa[kh + 1][rem], acc1);
        }
        float a0, a1, a2, a3;
        unpack2(a0, a1, acc0);
        unpack2(a2, a3, acc1);
        float mx = fmaxf(fmaxf(a0, a1), fmaxf(a2, a3));
        word |= ((u32)(mx >= thr[co])) << co;
    }
    g_act1[idx] = word;
}

// ---------------- layer 2: warp = 2 positions, lane = 2 channels -----------------
__device__ __forceinline__ int w9(const u32 (&a)[4][4], const u32 (&w)[9], int dy, int dx) {
    return R9(a[dy][dx] ^ w[0], a[dy][dx + 1] ^ w[1], a[dy][dx + 2] ^ w[2],
              a[dy + 1][dx] ^ w[3], a[dy + 1][dx + 1] ^ w[4], a[dy + 1][dx + 2] ^ w[5],
              a[dy + 2][dx] ^ w[6], a[dy + 2][dx + 1] ^ w[7], a[dy + 2][dx + 2] ^ w[8]);
}

__global__ __launch_bounds__(256) void k_layer2() {
    int gt = blockIdx.x * 256 + threadIdx.x;
    int gw = gt >> 5, lane = gt & 31;
    int pq = gw & 15;                  // pair index: pw0 = 2*pq
    int bp = gw >> 4;                  // b*31 + ph
    int b = bp / 31, ph = bp % 31;
    int pw0 = 2 * pq;

    u32 wA[9], wB[9];
    #pragma unroll
    for (int t = 0; t < 9; t++) {
        wA[t] = g_w2b[lane * 9 + t];
        wB[t] = g_w2b[(lane + 32) * 9 + t];
    }
    int ithrA = (int)ceilf(g_thr2[lane]);
    int ithrB = (int)ceilf(g_thr2[lane + 32]);
    int pthrA = (288 - ithrA) >> 1;
    int pthrB = (288 - ithrB) >> 1;

    const u32* rbase = g_act1 + b * 3969 + (2 * ph - 1) * 63;
    bool rv0 = (ph > 0), cv0 = (pw0 > 0);

    u32 a[4][4];
    #pragma unroll
    for (int i = 0; i < 4; i++) {
        bool rv = (i > 0) || rv0;
        #pragma unroll
        for (int j = 0; j < 4; j++) {
            bool cv = (j > 0) || cv0;
            a[i][j] = (rv && cv) ? rbase[i * 63 + 2 * pw0 - 1 + j] : 0u;
        }
    }

    // position 0
    int PA[4], PB[4];
    #pragma unroll
    for (int dy = 0; dy < 2; dy++)
        #pragma unroll
        for (int dx = 0; dx < 2; dx++) {
            PA[dy * 2 + dx] = w9(a, wA, dy, dx);
            PB[dy * 2 + dx] = w9(a, wB, dy, dx);
        }
    bool bitA0, bitB0;
    if (rv0 && cv0) {
        bitA0 = min(min(PA[0], PA[1]), min(PA[2], PA[3])) <= pthrA;
        bitB0 = min(min(PB[0], PB[1]), min(PB[2], PB[3])) <= pthrB;
    } else {
        int ctA[9], ctB[9];
        #pragma unroll
        for (int t = 0; t < 9; t++) {
            ctA[t] = 32 - 2 * __popc(wA[t]);
            ctB[t] = 32 - 2 * __popc(wB[t]);
        }
        int topA = ctA[0] + ctA[1] + ctA[2], leftA = ctA[0] + ctA[3] + ctA[6];
        int topB = ctB[0] + ctB[1] + ctB[2], leftB = ctB[0] + ctB[3] + ctB[6];
        int cTA = rv0 ? 0 : topA, cLA = cv0 ? 0 : leftA, c0A = (!rv0 && !cv0) ? ctA[0] : 0;
        int cTB = rv0 ? 0 : topB, cLB = cv0 ? 0 : leftB, c0B = (!rv0 && !cv0) ? ctB[0] : 0;
        bitA0 = max(max(288 - 2 * PA[0] - (cTA + cLA - c0A), 288 - 2 * PA[1] - cTA),
                    max(288 - 2 * PA[2] - cLA, 288 - 2 * PA[3])) >= ithrA;
        bitB0 = max(max(288 - 2 * PB[0] - (cTB + cLB - c0B), 288 - 2 * PB[1] - cTB),
                    max(288 - 2 * PB[2] - cLB, 288 - 2 * PB[3])) >= ithrB;
    }
    u32 wA0 = __ballot_sync(0xffffffffu, bitA0);
    u32 wB0 = __ballot_sync(0xffffffffu, bitB0);
    int p0 = b * 961 + ph * 31 + pw0;
    if (lane == 0) ((uint2*)g_act2)[p0] = make_uint2(wA0, wB0);

    if (pw0 < 30) {   // position 1 (pw0+1): always interior in x
        #pragma unroll
        for (int i = 0; i < 4; i++) {
            bool rv = (i > 0) || rv0;
            a[i][0] = a[i][2]; a[i][1] = a[i][3];
            a[i][2] = rv ? rbase[i * 63 + 2 * pw0 + 3] : 0u;
            a[i][3] = rv ? rbase[i * 63 + 2 * pw0 + 4] : 0u;
        }
        #pragma unroll
        for (int dy = 0; dy < 2; dy++)
            #pragma unroll
            for (int dx = 0; dx < 2; dx++) {
                PA[dy * 2 + dx] = w9(a, wA, dy, dx);
                PB[dy * 2 + dx] = w9(a, wB, dy, dx);
            }
        bool bitA1, bitB1;
        if (rv0) {
            bitA1 = min(min(PA[0], PA[1]), min(PA[2], PA[3])) <= pthrA;
            bitB1 = min(min(PB[0], PB[1]), min(PB[2], PB[3])) <= pthrB;
        } else {
            int topA = 0, topB = 0;
            #pragma unroll
            for (int t = 0; t < 3; t++) {
                topA += 32 - 2 * __popc(wA[t]);
                topB += 32 - 2 * __popc(wB[t]);
            }
            bitA1 = max(max(288 - 2 * PA[0] - topA, 288 - 2 * PA[1] - topA),
                        max(288 - 2 * PA[2], 288 - 2 * PA[3])) >= ithrA;
            bitB1 = max(max(288 - 2 * PB[0] - topB, 288 - 2 * PB[1] - topB),
                        max(288 - 2 * PB[2], 288 - 2 * PB[3])) >= ithrB;
        }
        u32 wA1 = __ballot_sync(0xffffffffu, bitA1);
        u32 wB1 = __ballot_sync(0xffffffffu, bitB1);
        if (lane == 0) ((uint2*)g_act2)[p0 + 1] = make_uint2(wA1, wB1);
    }
}

// ---------------- layer 3: warp = (2 positions, cow) -----------------------------
__global__ __launch_bounds__(256) void k_layer3() {
    int gt = blockIdx.x * 256 + threadIdx.x;
    int gw = gt >> 5, lane = gt & 31;
    int cow = gw & 3;
    int t1 = gw >> 2;
    int pq = t1 & 7;                  // pw0 = 2*pq
    int bp = t1 >> 3;                 // b*15 + ph
    int b = bp / 15, ph = bp % 15;
    int co = cow * 32 + lane;
    int pw0 = 2 * pq;

    uint2 w[9];
    #pragma unroll
    for (int t = 0; t < 9; t++) w[t] = ((const uint2*)g_w3b)[co * 9 + t];
    int ithr = (int)ceilf(g_thr3[co]);
    int pthr = (576 - ithr) >> 1;

    const uint2* rbase = (const uint2*)g_act2 + b * 961 + (2 * ph - 1) * 31;
    bool rv0 = (ph > 0), cv0 = (pw0 > 0);
    uint2 z = make_uint2(0u, 0u);

    uint2 a[4][4];
    #pragma unroll
    for (int i = 0; i < 4; i++) {
        bool rv = (i > 0) || rv0;
        #pragma unroll
        for (int j = 0; j < 4; j++) {
            bool cv = (j > 0) || cv0;
            a[i][j] = (rv && cv) ? rbase[i * 31 + 2 * pw0 - 1 + j] : z;
        }
    }

    // position 0
    int P0 = win18<0, 0>(a, w), P1 = win18<0, 1>(a, w);
    int P2 = win18<1, 0>(a, w), P3 = win18<1, 1>(a, w);
    bool bit0;
    if (rv0 && cv0) {
        bit0 = min(min(P0, P1), min(P2, P3)) <= pthr;
    } else {
        int ct[9];
        #pragma unroll
        for (int t = 0; t < 9; t++) ct[t] = 64 - 2 * (__popc(w[t].x) + __popc(w[t].y));
        int top = ct[0] + ct[1] + ct[2], left = ct[0] + ct[3] + ct[6];
        int cT = rv0 ? 0 : top, cL = cv0 ? 0 : left, c0 = (!rv0 && !cv0) ? ct[0] : 0;
        bit0 = max(max(576 - 2 * P0 - (cT + cL - c0), 576 - 2 * P1 - cT),
                   max(576 - 2 * P2 - cL, 576 - 2 * P3)) >= ithr;
    }
    u32 word0 = __ballot_sync(0xffffffffu, bit0);
    int p0 = b * 225 + ph * 15 + pw0;
    if (lane == 0) g_act3[p0 * 4 + cow] = word0;

    if (pw0 < 14) {    // position 1
        #pragma unroll
        for (int i = 0; i < 4; i++) {
            bool rv = (i > 0) || rv0;
            a[i][0] = a[i][2]; a[i][1] = a[i][3];
            a[i][2] = rv ? rbase[i * 31 + 2 * pw0 + 3] : z;
            a[i][3] = rv ? rbase[i * 31 + 2 * pw0 + 4] : z;
        }
        P0 = win18<0, 0>(a, w); P1 = win18<0, 1>(a, w);
        P2 = win18<1, 0>(a, w); P3 = win18<1, 1>(a, w);
        bool bit1;
        if (rv0) {
            bit1 = min(min(P0, P1), min(P2, P3)) <= pthr;
        } else {
            int top = 0;
            #pragma unroll
            for (int t = 0; t < 3; t++) top += 64 - 2 * (__popc(w[t].x) + __popc(w[t].y));
            bit1 = max(max(576 - 2 * P0 - top, 576 - 2 * P1 - top),
                       max(576 - 2 * P2, 576 - 2 * P3)) >= ithr;
        }
        u32 word1 = __ballot_sync(0xffffffffu, bit1);
        if (lane == 0) g_act3[(p0 + 1) * 4 + cow] = word1;
    }
}

// ---------------- layer 4: warp = (2 positions, cow), 2 halves -------------------
__global__ __launch_bounds__(256) void k_layer4(
        const float* __restrict__ m4, const float* __restrict__ v4,
        const float* __restrict__ b4, float* __restrict__ out) {
    int gt = blockIdx.x * 256 + threadIdx.x;
    int gw = gt >> 5, lane = gt & 31;
    int cow = gw & 7;
    int t1 = gw >> 3;
    int pq = t1 & 3;                  // pw0 = 2*pq
    int bp = t1 >> 2;                 // b*7 + ph
    int b = bp / 7, ph = bp % 7;
    int co = cow * 32 + lane;
    int pw0 = 2 * pq;

    const uint2* act = (const uint2*)g_act3;
    bool rv0 = (ph > 0), cv0 = (pw0 > 0);
    uint2 z = make_uint2(0u, 0u);

    int P[4] = {0, 0, 0, 0}, Q[4] = {0, 0, 0, 0};
    #pragma unroll
    for (int h = 0; h < 2; h++) {
        uint2 w[9];
        #pragma unroll
        for (int t = 0; t < 9; t++) w[t] = ((const uint2*)g_w4b)[(co * 9 + t) * 2 + h];

        uint2 a[4][4];
        #pragma unroll
        for (int i = 0; i < 4; i++) {
            bool rv = (i > 0) || rv0;
            #pragma unroll
            for (int j = 0; j < 4; j++) {
                bool cv = (j > 0) || cv0;
                int rr = 2 * ph - 1 + i, cc = 2 * pw0 - 1 + j;
                a[i][j] = (rv && cv) ? act[(b * 225 + rr * 15 + cc) * 2 + h] : z;
            }
        }
        P[0] += win18<0, 0>(a, w); P[1] += win18<0, 1>(a, w);
        P[2] += win18<1, 0>(a, w); P[3] += win18<1, 1>(a, w);

        if (pw0 < 6) {
            #pragma unroll
            for (int i = 0; i < 4; i++) {
                bool rv = (i > 0) || rv0;
                int rr = 2 * ph - 1 + i;
                a[i][0] = a[i][2]; a[i][1] = a[i][3];
                a[i][2] = rv ? act[(b * 225 + rr * 15 + 2 * pw0 + 3) * 2 + h] : z;
                a[i][3] = rv ? act[(b * 225 + rr * 15 + 2 * pw0 + 4) * 2 + h] : z;
            }
            Q[0] += win18<0, 0>(a, w); Q[1] += win18<0, 1>(a, w);
            Q[2] += win18<1, 0>(a, w); Q[3] += win18<1, 1>(a, w);
        }
    }

    float mean = m4[co];
    float rstd = rsqrtf(v4[co] + BN_EPS);
    float beta = b4[co];
    float* outp = out + (b * 49 + ph * 7 + pw0) * 256 + co;

    int ct[9], top = 0, left = 0;
    if (!rv0 || !cv0) {
        #pragma unroll
        for (int t = 0; t < 9; t++) {
            uint4 wt = ((const uint4*)g_w4b)[co * 9 + t];
            ct[t] = 128 - 2 * (__popc(wt.x) + __popc(wt.y) + __popc(wt.z) + __popc(wt.w));
        }
        top = ct[0] + ct[1] + ct[2]; left = ct[0] + ct[3] + ct[6];
    }

    int best0;
    if (rv0 && cv0) {
        best0 = 1152 - 2 * min(min(P[0], P[1]), min(P[2], P[3]));
    } else {
        int cT = rv0 ? 0 : top, cL = cv0 ? 0 : left, c0 = (!rv0 && !cv0) ? ct[0] : 0;
        best0 = max(max(1152 - 2 * P[0] - (cT + cL - c0), 1152 - 2 * P[1] - cT),
                    max(1152 - 2 * P[2] - cL, 1152 - 2 * P[3]));
    }
    outp[0] = ((float)best0 - mean) * rstd + beta;

    if (pw0 < 6) {
        int best1;
        if (rv0) {
            best1 = 1152 - 2 * min(min(Q[0], Q[1]), min(Q[2], Q[3]));
        } else {
            best1 = max(max(1152 - 2 * Q[0] - top, 1152 - 2 * Q[1] - top),
                        max(1152 - 2 * Q[2], 1152 - 2 * Q[3]));
        }
        outp[256] = ((float)best1 - mean) * rstd + beta;
    }
}

// ---------------- launch ----------------
extern "C" void kernel_launch(void* const* d_in, const int* in_sizes, int n_in,
                              void* d_out, int out_size) {
    const float* x  = (const float*)d_in[0];
    const float* w1 = (const float*)d_in[1];
    const float* m1 = (const float*)d_in[2];
    const float* v1 = (const float*)d_in[3];
    const float* b1 = (const float*)d_in[4];
    const float* w2 = (const float*)d_in[5];
    const float* m2 = (const float*)d_in[6];
    const float* v2 = (const float*)d_in[7];
    const float* b2 = (const float*)d_in[8];
    const float* w3 = (const float*)d_in[9];
    const float* m3 = (const float*)d_in[10];
    const float* v3 = (const float*)d_in[11];
    const float* b3 = (const float*)d_in[12];
    const float* w4 = (const float*)d_in[13];
    const float* m4 = (const float*)d_in[14];
    const float* v4 = (const float*)d_in[15];
    const float* b4 = (const float*)d_in[16];
    float* out = (float*)d_out;

    k_layer1<<<NB1 + 48, 256>>>(x, w1, m1, v1, b1, w2, w3, w4, m2, v2, b2, m3, v3, b3);
    k_layer2<<<64 * 31 * 16 * 32 / 256, 256>>>();            // 3968 blocks
    k_layer3<<<64 * 15 * 8 * 4 * 32 / 256, 256>>>();         // 3840 blocks
    k_layer4<<<64 * 7 * 4 * 8 * 32 / 256, 256>>>(m4, v4, b4, out);  // 896 blocks
}